// round 17
// baseline (speedup 1.0000x reference)
#include <cuda_runtime.h>
#include <cuda_fp16.h>
#include <cstdint>
#include <math.h>

#define DO_   30
#define TPB   256

// smem (bytes):
//   [0, 27648)       weights fp16 [tap][32 co x 16 cin] (1KB per tap, XOR-swizzled)
//   [27648, 83136)   slab: 3 d-slices of 18496B (578 rows x 32B, XOR-swizzled)
// epilogue overlays floats at [0, 67584)
#define SMEM_DYN 83136
#define SLAB0    27648
#define SLCSZ    18496

__device__ __forceinline__ uint32_t smem_u32(const void* p) {
    uint32_t a;
    asm("{ .reg .u64 t; cvta.to.shared.u64 t, %1; cvt.u32.u64 %0, t; }" : "=r"(a) : "l"(p));
    return a;
}
__device__ __forceinline__ void ldsm4(uint32_t* r, uint32_t addr) {
    asm volatile("ldmatrix.sync.aligned.m8n8.x4.shared.b16 {%0,%1,%2,%3}, [%4];"
        : "=r"(r[0]), "=r"(r[1]), "=r"(r[2]), "=r"(r[3]) : "r"(addr));
}
__device__ __forceinline__ void mma_f16(float* c, const uint32_t* a, const uint32_t* b) {
    asm volatile(
        "mma.sync.aligned.m16n8k16.row.col.f32.f16.f16.f32 "
        "{%0,%1,%2,%3}, {%4,%5,%6,%7}, {%8,%9}, {%0,%1,%2,%3};"
        : "+f"(c[0]), "+f"(c[1]), "+f"(c[2]), "+f"(c[3])
        : "r"(a[0]), "r"(a[1]), "r"(a[2]), "r"(a[3]), "r"(b[0]), "r"(b[1]));
}

// Row's two 16B chunks live at chunk ^ ((row>>2)&1): conflict-free ldmatrix.
__device__ __forceinline__ uint32_t swz(uint32_t row, uint32_t chunk16) {
    return row * 32u + (chunk16 ^ ((row & 4u) << 2));
}

__global__ __launch_bounds__(TPB, 2) void conv_fused(
    const float* __restrict__ x,
    const float* __restrict__ wsrc,
    const float* __restrict__ cbias,
    const float* __restrict__ sfac,
    const float* __restrict__ bparm,
    float* __restrict__ out)
{
    extern __shared__ char sm[];
    __shared__ float e0[32], e1[32], e2n[32];

    const int d0 = blockIdx.x, b = blockIdx.y, hh = blockIdx.z;
    const int t = threadIdx.x, warp = t >> 5, lane = t & 31;
    const uint32_t smb = smem_u32(sm);
    const uint32_t ws_a = smb;
    const uint32_t sl_a = smb + SLAB0;

    const int hstart = hh * 16;
    const int rows_h = hh ? 16 : 18;      // input h-rows (halo below; clipped)

    if (t < 32) {
        const float s = sfac[t];
        e0[t] = cbias[t] * s;
        e1[t] = s;
        e2n[t] = -1.4426950408889634f * bparm[t];   // -log2(e) * bias_param
    }

    // ---- convert weights: OIDHW fp32 -> swizzled [tap][co][cin] fp16 in smem.
    // i = (co*16+cin)*27 + tap  (linear over wsrc -> coalesced)
    for (int i = t; i < 13824; i += TPB) {
        const int co  = i / 432;
        const int r   = i - co * 432;
        const int cin = r / 27;
        const int tap = r - cin * 27;
        const uint32_t off = (uint32_t)tap * 1024u + (uint32_t)co * 32u
                           + (((uint32_t)cin * 2u) ^ (((uint32_t)co & 4u) << 2));
        *(__half*)(sm + off) = __float2half_rn(wsrc[i]);
    }

    // ---- convert x: NCDHW fp32 -> swizzled slab [slice][h*32+w][cin] fp16.
    // unit u: w4idx = u&7 (lanes -> consecutive w: coalesced LDG.128),
    //         cquad = (u>>3)&3 (4 cin), hidx = u>>5 -> (slice, h)
    {
        const int units = 3 * rows_h * 32;
        const float* xb = x + (long)b * 16 * 32768 + (long)d0 * 1024 + (long)hstart * 32;
        for (int u = t; u < units; u += TPB) {
            const int w4 = (u & 7) * 4;
            const int cq = (u >> 3) & 3;
            const int hidx = u >> 5;
            const int slice = hidx / rows_h;
            const int h = hidx - slice * rows_h;

            const float* xp = xb + (long)slice * 1024 + (long)h * 32 + w4
                                 + (long)(cq * 4) * 32768;
            float a0[4], a1[4], a2[4], a3[4];
            *(float4*)a0 = *(const float4*)xp;
            *(float4*)a1 = *(const float4*)(xp + 32768);
            *(float4*)a2 = *(const float4*)(xp + 2 * 32768);
            *(float4*)a3 = *(const float4*)(xp + 3 * 32768);

            // row = h*32 + w4 + k; k<4 and w4%4==0 => row&4 == w4&4 for all k
            const uint32_t xorb = (((uint32_t)w4 & 4u) << 2);
            const uint32_t dbase = (uint32_t)SLAB0 + (uint32_t)slice * SLCSZ
                                 + (uint32_t)(h * 32 + w4) * 32u
                                 + (((uint32_t)cq * 8u) ^ xorb);
            #pragma unroll
            for (int k = 0; k < 4; ++k) {
                __half2 p01 = __floats2half2_rn(a0[k], a1[k]);
                __half2 p23 = __floats2half2_rn(a2[k], a3[k]);
                uint2 st;
                st.x = *(uint32_t*)&p01;
                st.y = *(uint32_t*)&p23;
                *(uint2*)(sm + dbase + (uint32_t)k * 32u) = st;
            }
        }
    }

    float acc[4][4][4];
    #pragma unroll
    for (int rt = 0; rt < 4; ++rt)
        #pragma unroll
        for (int j = 0; j < 4; ++j)
            #pragma unroll
            for (int k = 0; k < 4; ++k)
                acc[rt][j][k] = 0.0f;

    const uint32_t bn = (lane & 7) + ((lane & 16) >> 1);
    const uint32_t bc = (lane & 8) * 2;
    const uint32_t ar = (lane & 15);
    const uint32_t ac = (lane & 16);

    const uint32_t bofs  = swz(bn, bc);
    const uint32_t bofs2 = swz(bn + 16u, bc);
    const uint32_t awbase = (uint32_t)(warp * 64) + ar;

    __syncthreads();

    // ---- mainloop: 27 taps, fully unrolled, A double-buffered (R14 structure)
    uint32_t ah[2][4][4];
    uint32_t bh[4][2];

    {   // preload A for tap 0
        const uint32_t arow0 = awbase;
        const uint32_t axor = ac ^ ((arow0 & 4u) << 2);
        #pragma unroll
        for (int rt = 0; rt < 4; ++rt)
            ldsm4(ah[0][rt], sl_a + (arow0 + (uint32_t)rt * 16u) * 32u + axor);
    }

    #pragma unroll
    for (int tap = 0; tap < 27; ++tap) {
        const int buf = tap & 1;

        {   // B fragments for current tap
            const uint32_t base = ws_a + (uint32_t)tap * 1024u;
            uint32_t r0[4], r1[4];
            ldsm4(r0, base + bofs);
            ldsm4(r1, base + bofs2);
            bh[0][0] = r0[0]; bh[0][1] = r0[1]; bh[1][0] = r0[2]; bh[1][1] = r0[3];
            bh[2][0] = r1[0]; bh[2][1] = r1[1]; bh[3][0] = r1[2]; bh[3][1] = r1[3];
        }

        // prefetch A for tap+1
        if (tap + 1 < 27) {
            const int nt = tap + 1;
            const int nkd = nt / 9, nr = nt - nkd * 9;
            const int nkh = nr / 3, nkw = nr - nkh * 3;
            const uint32_t arow0 = awbase + (uint32_t)(nkh * 32 + nkw);
            const uint32_t axor = ac ^ ((arow0 & 4u) << 2);
            const uint32_t kd_a = sl_a + (uint32_t)nkd * SLCSZ;
            #pragma unroll
            for (int rt = 0; rt < 4; ++rt)
                ldsm4(ah[buf ^ 1][rt], kd_a + (arow0 + (uint32_t)rt * 16u) * 32u + axor);
        }

        #pragma unroll
        for (int rt = 0; rt < 4; ++rt)
            #pragma unroll
            for (int j = 0; j < 4; ++j)
                mma_f16(acc[rt][j], ah[buf][rt], bh[j]);
    }

    // ---- epilogue: stage accumulators to smem (pitch 33), then coalesced store
    __syncthreads();
    float* ep = (float*)sm;
    const int g  = lane >> 2;
    const int cq = 2 * (lane & 3);
    #pragma unroll
    for (int rt = 0; rt < 4; ++rt) {
        const int R = warp * 64 + rt * 16 + g;
        #pragma unroll
        for (int j = 0; j < 4; ++j) {
            const int col = j * 8 + cq;
            ep[R * 33 + col]           = acc[rt][j][0];
            ep[R * 33 + col + 1]       = acc[rt][j][1];
            ep[(R + 8) * 33 + col]     = acc[rt][j][2];
            ep[(R + 8) * 33 + col + 1] = acc[rt][j][3];
        }
    }
    __syncthreads();

    #pragma unroll
    for (int half = 0; half < 2; ++half) {
        const int r = half * 256 + t;
        const int h = hstart + (r >> 5);
        const int w = r & 31;
        if (w < 30 && h < 30) {
            float* ob = out + (((long)b * 32 * DO_ + d0) * 30 + h) * 30 + w;
            #pragma unroll 8
            for (int co = 0; co < 32; ++co) {
                const float v = ep[r * 33 + co];
                const float y = fmaf(v, e1[co], e0[co]);
                float th; asm("tanh.approx.f32 %0, %1;" : "=f"(th) : "f"(y));
                const float z = th * e2n[co];
                float ex; asm("ex2.approx.f32 %0, %1;" : "=f"(ex) : "f"(z));
                float sg; asm("rcp.approx.f32 %0, %1;" : "=f"(sg) : "f"(1.0f + ex));
                ob[(long)co * (DO_ * 30 * 30)] = sg;
            }
        }
    }
}

// ---------------- launch: ONE kernel, no prepass, no intermediates ----------------
extern "C" void kernel_launch(void* const* d_in, const int* in_sizes, int n_in,
                              void* d_out, int out_size)
{
    const float* x  = (const float*)d_in[0];
    const float* w  = (const float*)d_in[1];
    const float* cb = (const float*)d_in[2];
    const float* sf = (const float*)d_in[3];
    const float* bp = (const float*)d_in[4];
    float* out      = (float*)d_out;

    cudaFuncSetAttribute(conv_fused, cudaFuncAttributeMaxDynamicSharedMemorySize, SMEM_DYN);

    dim3 grid(DO_, 16, 2);
    conv_fused<<<grid, TPB, SMEM_DYN>>>(x, w, cb, sf, bp, out);
}